// round 15
// baseline (speedup 1.0000x reference)
#include <cuda_runtime.h>
#include <cuda_fp16.h>
#include <stdint.h>

// ---------------------------------------------------------------------------
// 2-layer GCN, single persistent kernel. Round 15: half-warp row ownership.
// Each 16-lane half-warp owns a full row (row = 128B = 16 x u64 for both
// layers): no cross-slot shfl reduction, no slot predicates, two independent
// gather streams per warp. Base otherwise identical to round 13 (best).
// ---------------------------------------------------------------------------

#define N_MAXC  100000
#define E_MAXC  1700000
#define FIN1    128
#define HID     64
#define CLS     32
#define NB      512
#define BS      256
#define NT      (NB * BS)

typedef unsigned long long u64;
typedef unsigned int u32;

// ---- device scratch ----
__device__ u64        g_degcnt[N_MAXC];        // (count<<42)|fixed24(sum ew); 0 at entry
__device__ u32        g_slot[E_MAXC];
__device__ int        g_rowptr[N_MAXC + 1];    // intra-chunk exclusive counts
__device__ float      g_dinv[N_MAXC];
__device__ int        g_bsums[NB];
__device__ u64        g_csr[E_MAXC];           // (f32bits(ew)<<32)|src
__device__ u64        g_xw1h[(size_t)N_MAXC * 16];  // fp16 permuted xw1, 12.8MB
__device__ ulonglong2 g_xw2v[(size_t)N_MAXC * 8];   // fp32 xw2
__device__ int        g_tickets[4];            // monotonic across runs
__device__ int        g_count;
__device__ int        g_gen;

// ---- packed f32x2 helpers ----
__device__ __forceinline__ u64 ffma2(u64 a, u64 b, u64 c) {
    u64 d;
    asm("fma.rn.f32x2 %0, %1, %2, %3;" : "=l"(d) : "l"(a), "l"(b), "l"(c));
    return d;
}
__device__ __forceinline__ u64 dup2(u32 w) {
    u64 d;
    asm("mov.b64 %0, {%1, %1};" : "=l"(d) : "r"(w));
    return d;
}
__device__ __forceinline__ u64 pack2f(float x, float y) {
    u64 d;
    asm("mov.b64 %0, {%1, %2};" : "=l"(d) : "r"(__float_as_uint(x)), "r"(__float_as_uint(y)));
    return d;
}
__device__ __forceinline__ float2 unpk(u64 v) {
    float2 f;
    asm("mov.b64 {%0, %1}, %2;" : "=f"(f.x), "=f"(f.y) : "l"(v));
    return f;
}
__device__ __forceinline__ u32 f2h2(float lo, float hi) {
    u32 r;
    asm("cvt.rn.f16x2.f32 %0, %1, %2;" : "=r"(r) : "f"(hi), "f"(lo));
    return r;
}
__device__ __forceinline__ float2 h2f2(u32 v) {
    __half2 h = *(__half2*)&v;
    return __half22float2(h);
}

// ---- grid barrier ----
__device__ __forceinline__ void gbar(int expect) {
    __syncthreads();
    if (threadIdx.x == 0) {
        __threadfence();
        int t = atomicAdd(&g_count, 1);
        if (t == NB - 1) {
            g_count = 0;
            __threadfence();
            *(volatile int*)&g_gen = expect;
        } else {
            while (*(volatile int*)&g_gen - expect < 0) {}
            __threadfence();
        }
    }
    __syncthreads();
}

__global__ void __launch_bounds__(BS, 4) mega(
    const float* __restrict__ x, const void* __restrict__ ei,
    const float* __restrict__ ew, const float* __restrict__ W1,
    const float* __restrict__ b1, const float* __restrict__ W2,
    const float* __restrict__ b2, float* __restrict__ out,
    int N, int E)
{
    __shared__ __align__(16) char s_mem[33792 + 4096];
    __shared__ int s_is64, s_tile, s_tb0, s_tb1, s_tb2;

    float* sX   = (float*)s_mem;                  // GEMM: [64][132]
    float* sW   = (float*)(s_mem + 33792);        // GEMM: [16][64]
    u32*   sEpiH = (u32*)s_mem;                   // GEMM epi: [64][33] u32 (half2)
    int*   s_scan = (int*)s_mem;                  // C scan
    u64*   s_w2a = (u64*)s_mem;                   // proj pairs lo
    u64*   s_w2b = (u64*)(s_mem + 4096);          // proj pairs hi
    u64 (*s_ebuf)[32] = (u64(*)[32])(s_mem + 8192);           // 8 x 32 u64
    float (*s_hrow)[2 * HID] = (float(*)[2 * HID])(s_mem + 8192 + 2048); // 8 x 128 f
    int*   s_pfx = (int*)(s_mem + 16384);         // block prefix, persists F..H

    const int tid = threadIdx.x;
    const int b   = blockIdx.x;
    const int gtid = b * BS + tid;
    const int wid = tid >> 5, lane = tid & 31;

    // ---------------- entry: bases + i32/i64 detect -------------------------
    int ebase = 0;
    if (tid == 0) {
        ebase = *(volatile int*)&g_gen;
        s_tb0 = *(volatile int*)&g_tickets[0];
        s_tb1 = *(volatile int*)&g_tickets[1];
        s_tb2 = *(volatile int*)&g_tickets[2];
    }
    if (tid < 32) {
        const u32* u = (const u32*)ei;
        int cnt = E < 64 ? E : 64;
        bool nz = false;
        for (int j = tid; j < cnt; j += 32) nz |= (u[2 * j + 1] != 0u);
        u32 bl = __ballot_sync(0xffffffffu, nz);
        if (tid == 0) s_is64 = (bl == 0u) ? 1 : 0;
    }
    gbar(ebase + 1);
    const int is64 = s_is64;

    // ---------------- phase B: edge atomics+slots overlapped with GEMM ------
    for (int e = gtid; e < E; e += NT) {
        int d = is64 ? (int)((const long long*)ei)[(size_t)E + e]
                     : ((const int*)ei)[(size_t)E + e];
        u64 add = (1ull << 42) | (u64)(u32)__float2uint_rn(ew[e] * 16777216.0f);
        u64 old = atomicAdd(&g_degcnt[d], add);
        g_slot[e] = (u32)(old >> 42);
    }
    {
        const int ntiles = (N + 63) / 64;
        const int w8 = wid * 8;
        for (;;) {
            if (tid == 0) s_tile = atomicAdd(&g_tickets[0], 1) - s_tb0;
            __syncthreads();
            const int tile = s_tile;
            if (tile >= ntiles) break;
            const int row0 = tile * 64;
            for (int i = tid; i < 2048; i += BS) {
                int r = i >> 5, k4 = i & 31;
                float4 v = make_float4(0.f, 0.f, 0.f, 0.f);
                if (row0 + r < N)
                    v = ((const float4*)(x + (size_t)(row0 + r) * FIN1))[k4];
                *(float4*)&sX[r * 132 + 4 * k4] = v;
            }
            __syncthreads();

            u64 accA[4], accB[4];
#pragma unroll
            for (int j = 0; j < 4; j++) { accA[j] = 0ull; accB[j] = 0ull; }

            for (int c = 0; c < 8; c++) {
                {
                    int k = tid >> 4, c4 = tid & 15;
                    *(float4*)&sW[k * 64 + 4 * c4] =
                        ((const float4*)(W1 + (size_t)(c * 16 + k) * HID))[c4];
                }
                __syncthreads();
                const float4* xpA = (const float4*)&sX[lane * 132 + c * 16];
                const float4* xpB = (const float4*)&sX[(lane + 32) * 132 + c * 16];
#pragma unroll
                for (int k4 = 0; k4 < 4; k4++) {
                    float4 xa = xpA[k4];
                    float4 xb = xpB[k4];
                    float xsA[4] = {xa.x, xa.y, xa.z, xa.w};
                    float xsB[4] = {xb.x, xb.y, xb.z, xb.w};
#pragma unroll
                    for (int kk = 0; kk < 4; kk++) {
                        int k = k4 * 4 + kk;
                        ulonglong2 wv0 = *(const ulonglong2*)&sW[k * 64 + w8];
                        ulonglong2 wv1 = *(const ulonglong2*)&sW[k * 64 + w8 + 4];
                        u64 xA = dup2(__float_as_uint(xsA[kk]));
                        u64 xB = dup2(__float_as_uint(xsB[kk]));
                        accA[0] = ffma2(xA, wv0.x, accA[0]);
                        accA[1] = ffma2(xA, wv0.y, accA[1]);
                        accA[2] = ffma2(xA, wv1.x, accA[2]);
                        accA[3] = ffma2(xA, wv1.y, accA[3]);
                        accB[0] = ffma2(xB, wv0.x, accB[0]);
                        accB[1] = ffma2(xB, wv0.y, accB[1]);
                        accB[2] = ffma2(xB, wv1.x, accB[2]);
                        accB[3] = ffma2(xB, wv1.y, accB[3]);
                    }
                }
                __syncthreads();
            }
            // epilogue: f32x2 -> half2, transpose via smem, coalesced store
            {
                int cbase = (wid & 3) * 4;
                int hilo = (wid >> 2);
#pragma unroll
                for (int j = 0; j < 4; j++) {
                    float2 fa = unpk(accA[j]);
                    float2 fb = unpk(accB[j]);
                    int idx = 2 * (cbase + j) + hilo;
                    sEpiH[lane * 33 + idx] = f2h2(fa.x, fa.y);
                    sEpiH[(lane + 32) * 33 + idx] = f2h2(fb.x, fb.y);
                }
            }
            __syncthreads();
            u32* xw1u = (u32*)g_xw1h;
            for (int i = tid; i < 2048; i += BS) {
                int r = i >> 5, s = i & 31;
                if (row0 + r < N)
                    xw1u[(size_t)(row0 + r) * 32 + s] = sEpiH[r * 33 + s];
            }
            __syncthreads();
        }
    }
    gbar(ebase + 2);

    // ---------------- phase C: dinv + per-chunk(256) count scan -------------
    {
        const int r0 = b * 256 + tid;
        int c0 = 0;
        if (r0 < N) {
            u64 pc = g_degcnt[r0];
            c0 = (int)(pc >> 42);
            g_dinv[r0] = rsqrtf(1.0f + (float)(pc & ((1ull << 42) - 1)) * (1.0f / 16777216.0f));
        }
        s_scan[tid] = c0;
        __syncthreads();
        for (int off = 1; off < BS; off <<= 1) {
            int a = (tid >= off) ? s_scan[tid - off] : 0;
            __syncthreads();
            s_scan[tid] += a;
            __syncthreads();
        }
        if (r0 < N) g_rowptr[r0] = s_scan[tid] - c0;
        if (tid == BS - 1) g_bsums[b] = s_scan[BS - 1];
    }
    gbar(ebase + 3);

    // ---------------- phase F: block-prefix + fill + fp16 prescale ----------
    {
        int i0 = tid, i1 = tid + 256;
        int v0 = g_bsums[i0], v1 = g_bsums[i1];
        s_pfx[i0] = v0; s_pfx[i1] = v1;
        __syncthreads();
        for (int off = 1; off < 512; off <<= 1) {
            int a0 = (i0 >= off) ? s_pfx[i0 - off] : 0;
            int a1 = (i1 >= off) ? s_pfx[i1 - off] : 0;
            __syncthreads();
            s_pfx[i0] += a0; s_pfx[i1] += a1;
            __syncthreads();
        }
        s_pfx[i0] -= v0; s_pfx[i1] -= v1;
        __syncthreads();
    }
    for (int e = gtid; e < E; e += NT) {
        int s, d;
        if (is64) {
            const long long* p = (const long long*)ei;
            s = (int)p[e]; d = (int)p[(size_t)E + e];
        } else {
            const int* p = (const int*)ei;
            s = p[e]; d = p[(size_t)E + e];
        }
        int slot = g_rowptr[d] + s_pfx[d >> 8] + (int)g_slot[e];
        g_csr[slot] = ((u64)__float_as_uint(ew[e]) << 32) | (u32)s;
    }
    {
        u32* xw1u = (u32*)g_xw1h;
        for (int i = gtid; i < N * 32; i += NT) {     // prescale xw1 by dinv
            int row = i >> 5;
            float dn = g_dinv[row];
            float2 f = h2f2(xw1u[i]);
            xw1u[i] = f2h2(dn * f.x, dn * f.y);
        }
    }
    gbar(ebase + 4);

    // ---------------- phase G: SpMM1, half-warp row ownership + proj --------
    for (int i = tid; i < HID * CLS; i += BS) {
        int k = i >> 5, c = i & 31;
        float v = W2[k * CLS + c];
        int c2 = (k & 31) >> 1;
        float* base = (float*)((k >= 32) ? s_w2b : s_w2a);
        base[(c2 * 32 + c) * 2 + (k & 1)] = v;
    }
    __syncthreads();
    const int slot = lane >> 4, cc = lane & 15;
    const u32 hmask = slot ? 0xFFFF0000u : 0x0000FFFFu;
    float b1a = b1[2 * cc], b1b = b1[2 * cc + 1];
    float b1c = b1[32 + 2 * cc], b1d = b1[33 + 2 * cc];
    u64* bufh = s_ebuf[wid] + slot * 16;              // private per half
    float* hrow = s_hrow[wid];                        // 128 floats: rowA|rowB
    for (;;) {
        int chunk;
        if (lane == 0) chunk = atomicAdd(&g_tickets[1], 1) - s_tb1;
        chunk = __shfl_sync(0xffffffffu, chunk, 0);
        int row0c = chunk * 8;
        if (row0c >= N) break;
        for (int pr = 0; pr < 8; pr += 2) {
            const int rowA = row0c + pr;
            const int row = rowA + slot;              // this half's row
            const bool active = (row < N);
            float dn = 0.f, a0 = 0.f, a1 = 0.f, a2 = 0.f, a3 = 0.f;
            if (active) {
                dn = g_dinv[row];
                u64 sv = g_xw1h[(size_t)row * 16 + cc];   // prescaled self
                float2 flo = h2f2((u32)sv), fhi = h2f2((u32)(sv >> 32));
                a0 = flo.x; a1 = flo.y; a2 = fhi.x; a3 = fhi.y;
                int p = g_rowptr[row] + s_pfx[row >> 8];
                int pe = (row + 1 < N) ? (g_rowptr[row + 1] + s_pfx[(row + 1) >> 8]) : E;
                while (p < pe) {
                    int m = pe - p; if (m > 16) m = 16;
                    __syncwarp(hmask);
                    if (cc < m) bufh[cc] = g_csr[p + cc];
                    __syncwarp(hmask);
                    int t = 0;
                    for (; t + 8 <= m; t += 8) {
                        u64 q[8], v[8];
#pragma unroll
                        for (int i = 0; i < 8; i++) q[i] = bufh[t + i];
#pragma unroll
                        for (int i = 0; i < 8; i++)
                            v[i] = g_xw1h[(size_t)(u32)q[i] * 16 + cc];
#pragma unroll
                        for (int i = 0; i < 8; i++) {
                            float w = __uint_as_float((u32)(q[i] >> 32));
                            float2 flo2 = h2f2((u32)v[i]), fhi2 = h2f2((u32)(v[i] >> 32));
                            a0 = fmaf(w, flo2.x, a0); a1 = fmaf(w, flo2.y, a1);
                            a2 = fmaf(w, fhi2.x, a2); a3 = fmaf(w, fhi2.y, a3);
                        }
                    }
                    for (; t < m; t++) {
                        u64 q0 = bufh[t];
                        u64 v0 = g_xw1h[(size_t)(u32)q0 * 16 + cc];
                        float w = __uint_as_float((u32)(q0 >> 32));
                        float2 flo2 = h2f2((u32)v0), fhi2 = h2f2((u32)(v0 >> 32));
                        a0 = fmaf(w, flo2.x, a0); a1 = fmaf(w, flo2.y, a1);
                        a2 = fmaf(w, fhi2.x, a2); a3 = fmaf(w, fhi2.y, a3);
                    }
                    p += 16;
                }
            }
            __syncwarp();                             // both halves done
            if (active) {
                float hx = fmaxf(dn * a0 + b1a, 0.0f);
                float hy = fmaxf(dn * a1 + b1b, 0.0f);
                float hz = fmaxf(dn * a2 + b1c, 0.0f);
                float hw = fmaxf(dn * a3 + b1d, 0.0f);
                ((float4*)(hrow + slot * HID))[cc] = make_float4(hx, hy, hz, hw);
            }
            __syncwarp();
            // projection for rowA (all 32 lanes), then rowA+1
#pragma unroll 1
            for (int s2 = 0; s2 < 2; s2++) {
                int prow = rowA + s2;
                if (prow >= N) break;
                float dnp = g_dinv[prow];
                u64 accp = 0ull;
                const float4* hr = (const float4*)(hrow + s2 * HID);
#pragma unroll
                for (int c2 = 0; c2 < 16; c2++) {
                    float4 hv = hr[c2];
                    accp = ffma2(pack2f(hv.x, hv.y), s_w2a[c2 * 32 + lane], accp);
                    accp = ffma2(pack2f(hv.z, hv.w), s_w2b[c2 * 32 + lane], accp);
                }
                float2 ap = unpk(accp);
                ((float*)(g_xw2v + (size_t)prow * 8))[lane] = dnp * (ap.x + ap.y);
            }
            __syncwarp();                             // before hrow/buf reuse
        }
    }
    gbar(ebase + 5);

    // ---------------- phase H: SpMM2, half-warp row ownership -> out --------
    {
        float2 b2v = ((const float2*)b2)[cc];
        const u64* X2 = (const u64*)g_xw2v;
        for (;;) {
            int chunk;
            if (lane == 0) chunk = atomicAdd(&g_tickets[2], 1) - s_tb2;
            chunk = __shfl_sync(0xffffffffu, chunk, 0);
            int row0c = chunk * 8;
            if (row0c >= N) break;
            for (int pr = 0; pr < 8; pr += 2) {
                const int row = row0c + pr + slot;
                if (row >= N) continue;
                float dn = g_dinv[row];
                u64 acc = X2[(size_t)row * 16 + cc];      // prescaled self
                int p = g_rowptr[row] + s_pfx[row >> 8];
                int pe = (row + 1 < N) ? (g_rowptr[row + 1] + s_pfx[(row + 1) >> 8]) : E;
                while (p < pe) {
                    int m = pe - p; if (m > 16) m = 16;
                    __syncwarp(hmask);
                    if (cc < m) bufh[cc] = g_csr[p + cc];
                    __syncwarp(hmask);
                    int t = 0;
                    for (; t + 8 <= m; t += 8) {
                        u64 q[8], v[8];
#pragma unroll
                        for (int i = 0; i < 8; i++) q[i] = bufh[t + i];
#pragma unroll
                        for (int i = 0; i < 8; i++)
                            v[i] = X2[(size_t)(u32)q[i] * 16 + cc];
#pragma unroll
                        for (int i = 0; i < 8; i++)
                            acc = ffma2(dup2((u32)(q[i] >> 32)), v[i], acc);
                    }
                    for (; t < m; t++) {
                        u64 q0 = bufh[t];
                        acc = ffma2(dup2((u32)(q0 >> 32)),
                                    X2[(size_t)(u32)q0 * 16 + cc], acc);
                    }
                    p += 16;
                }
                float2 a = unpk(acc);
                ((float2*)(out + (size_t)row * CLS))[cc] =
                    make_float2(dn * a.x + b2v.x, dn * a.y + b2v.y);
            }
        }
    }

    // ---------------- tail: re-zero degcnt for the next replay --------------
    for (int i = gtid; i < N; i += NT) g_degcnt[i] = 0ull;
}

// ---------------------------------------------------------------------------
extern "C" void kernel_launch(void* const* d_in, const int* in_sizes, int n_in,
                              void* d_out, int out_size) {
    const float* x  = (const float*)d_in[0];
    const void*  ei = d_in[1];
    const float* ew = (const float*)d_in[2];
    const float* W1 = (const float*)d_in[3];
    const float* b1 = (const float*)d_in[4];
    const float* W2 = (const float*)d_in[5];
    const float* b2 = (const float*)d_in[6];
    float* out = (float*)d_out;

    int E = in_sizes[2];
    int N = in_sizes[0] / FIN1;
    if (N > N_MAXC) N = N_MAXC;
    if (E > E_MAXC) E = E_MAXC;

    mega<<<NB, BS>>>(x, ei, ew, W1, b1, W2, b2, out, N, E);
}

// round 16
// speedup vs baseline: 1.0323x; 1.0323x over previous
#include <cuda_runtime.h>
#include <cuda_fp16.h>
#include <stdint.h>

// ---------------------------------------------------------------------------
// 2-layer GCN, single persistent kernel. Round 16: LSU diet in SpMM.
// Four 8-lane edge slots per warp, one LDG.128 per edge-gather (row = 128B
// in both layers), LDS.64 decode, shfl_xor slot reduction. Base = round 13.
// ---------------------------------------------------------------------------

#define N_MAXC  100000
#define E_MAXC  1700000
#define FIN1    128
#define HID     64
#define CLS     32
#define NB      512
#define BS      256
#define NT      (NB * BS)

typedef unsigned long long u64;
typedef unsigned int u32;

// ---- device scratch ----
__device__ u64        g_degcnt[N_MAXC];        // (count<<42)|fixed24(sum ew); 0 at entry
__device__ u32        g_slot[E_MAXC];
__device__ int        g_rowptr[N_MAXC + 1];    // intra-chunk exclusive counts
__device__ float      g_dinv[N_MAXC];
__device__ int        g_bsums[NB];
__device__ u64        g_csr[E_MAXC];           // (f32bits(ew)<<32)|src
__device__ ulonglong2 g_xw1h2[(size_t)N_MAXC * 8];  // fp16 permuted xw1 (16B rows x8)
__device__ ulonglong2 g_xw2v[(size_t)N_MAXC * 8];   // fp32 xw2
__device__ int        g_tickets[4];            // monotonic across runs
__device__ int        g_count;
__device__ int        g_gen;

// ---- packed f32x2 helpers ----
__device__ __forceinline__ u64 ffma2(u64 a, u64 b, u64 c) {
    u64 d;
    asm("fma.rn.f32x2 %0, %1, %2, %3;" : "=l"(d) : "l"(a), "l"(b), "l"(c));
    return d;
}
__device__ __forceinline__ u64 dup2(u32 w) {
    u64 d;
    asm("mov.b64 %0, {%1, %1};" : "=l"(d) : "r"(w));
    return d;
}
__device__ __forceinline__ u64 pack2f(float x, float y) {
    u64 d;
    asm("mov.b64 %0, {%1, %2};" : "=l"(d) : "r"(__float_as_uint(x)), "r"(__float_as_uint(y)));
    return d;
}
__device__ __forceinline__ float2 unpk(u64 v) {
    float2 f;
    asm("mov.b64 {%0, %1}, %2;" : "=f"(f.x), "=f"(f.y) : "l"(v));
    return f;
}
__device__ __forceinline__ u32 f2h2(float lo, float hi) {
    u32 r;
    asm("cvt.rn.f16x2.f32 %0, %1, %2;" : "=r"(r) : "f"(hi), "f"(lo));
    return r;
}
__device__ __forceinline__ float2 h2f2(u32 v) {
    __half2 h = *(__half2*)&v;
    return __half22float2(h);
}

// ---- grid barrier ----
__device__ __forceinline__ void gbar(int expect) {
    __syncthreads();
    if (threadIdx.x == 0) {
        __threadfence();
        int t = atomicAdd(&g_count, 1);
        if (t == NB - 1) {
            g_count = 0;
            __threadfence();
            *(volatile int*)&g_gen = expect;
        } else {
            while (*(volatile int*)&g_gen - expect < 0) {}
            __threadfence();
        }
    }
    __syncthreads();
}

__global__ void __launch_bounds__(BS, 4) mega(
    const float* __restrict__ x, const void* __restrict__ ei,
    const float* __restrict__ ew, const float* __restrict__ W1,
    const float* __restrict__ b1, const float* __restrict__ W2,
    const float* __restrict__ b2, float* __restrict__ out,
    int N, int E)
{
    __shared__ __align__(16) char s_mem[33792 + 4096];
    __shared__ int s_is64, s_tile, s_tb0, s_tb1, s_tb2;

    float* sX   = (float*)s_mem;                  // GEMM: [64][132]
    float* sW   = (float*)(s_mem + 33792);        // GEMM: [16][64]
    u32*   sEpiH = (u32*)s_mem;                   // GEMM epi: [64][33] u32 (half2)
    int*   s_scan = (int*)s_mem;                  // C scan
    u64*   s_w2a = (u64*)s_mem;                   // proj pairs lo (4KB)
    u64*   s_w2b = (u64*)(s_mem + 4096);          // proj pairs hi (4KB)
    u64 (*s_ebuf)[32] = (u64(*)[32])(s_mem + 8192);           // 8 x 32 u64
    float (*s_hrow)[HID] = (float(*)[HID])(s_mem + 8192 + 2048);
    int*   s_pfx = (int*)(s_mem + 16384);         // block prefix (2KB), F..H
    float* s_b1v = (float*)(s_mem + 18432);       // 64 floats
    float* s_b2v = (float*)(s_mem + 18688);       // 32 floats

    const int tid = threadIdx.x;
    const int b   = blockIdx.x;
    const int gtid = b * BS + tid;
    const int wid = tid >> 5, lane = tid & 31;
    const u64* xw1u64 = (const u64*)g_xw1h2;

    // ---------------- entry: bases + i32/i64 detect -------------------------
    int ebase = 0;
    if (tid == 0) {
        ebase = *(volatile int*)&g_gen;
        s_tb0 = *(volatile int*)&g_tickets[0];
        s_tb1 = *(volatile int*)&g_tickets[1];
        s_tb2 = *(volatile int*)&g_tickets[2];
    }
    if (tid < 32) {
        const u32* u = (const u32*)ei;
        int cnt = E < 64 ? E : 64;
        bool nz = false;
        for (int j = tid; j < cnt; j += 32) nz |= (u[2 * j + 1] != 0u);
        u32 bl = __ballot_sync(0xffffffffu, nz);
        if (tid == 0) s_is64 = (bl == 0u) ? 1 : 0;
    }
    gbar(ebase + 1);
    const int is64 = s_is64;

    // ---------------- phase B: edge atomics+slots overlapped with GEMM ------
    for (int e = gtid; e < E; e += NT) {
        int d = is64 ? (int)((const long long*)ei)[(size_t)E + e]
                     : ((const int*)ei)[(size_t)E + e];
        u64 add = (1ull << 42) | (u64)(u32)__float2uint_rn(ew[e] * 16777216.0f);
        u64 old = atomicAdd(&g_degcnt[d], add);
        g_slot[e] = (u32)(old >> 42);
    }
    {
        const int ntiles = (N + 63) / 64;
        const int w8 = wid * 8;
        for (;;) {
            if (tid == 0) s_tile = atomicAdd(&g_tickets[0], 1) - s_tb0;
            __syncthreads();
            const int tile = s_tile;
            if (tile >= ntiles) break;
            const int row0 = tile * 64;
            for (int i = tid; i < 2048; i += BS) {
                int r = i >> 5, k4 = i & 31;
                float4 v = make_float4(0.f, 0.f, 0.f, 0.f);
                if (row0 + r < N)
                    v = ((const float4*)(x + (size_t)(row0 + r) * FIN1))[k4];
                *(float4*)&sX[r * 132 + 4 * k4] = v;
            }
            __syncthreads();

            u64 accA[4], accB[4];
#pragma unroll
            for (int j = 0; j < 4; j++) { accA[j] = 0ull; accB[j] = 0ull; }

            for (int c = 0; c < 8; c++) {
                {
                    int k = tid >> 4, c4 = tid & 15;
                    *(float4*)&sW[k * 64 + 4 * c4] =
                        ((const float4*)(W1 + (size_t)(c * 16 + k) * HID))[c4];
                }
                __syncthreads();
                const float4* xpA = (const float4*)&sX[lane * 132 + c * 16];
                const float4* xpB = (const float4*)&sX[(lane + 32) * 132 + c * 16];
#pragma unroll
                for (int k4 = 0; k4 < 4; k4++) {
                    float4 xa = xpA[k4];
                    float4 xb = xpB[k4];
                    float xsA[4] = {xa.x, xa.y, xa.z, xa.w};
                    float xsB[4] = {xb.x, xb.y, xb.z, xb.w};
#pragma unroll
                    for (int kk = 0; kk < 4; kk++) {
                        int k = k4 * 4 + kk;
                        ulonglong2 wv0 = *(const ulonglong2*)&sW[k * 64 + w8];
                        ulonglong2 wv1 = *(const ulonglong2*)&sW[k * 64 + w8 + 4];
                        u64 xA = dup2(__float_as_uint(xsA[kk]));
                        u64 xB = dup2(__float_as_uint(xsB[kk]));
                        accA[0] = ffma2(xA, wv0.x, accA[0]);
                        accA[1] = ffma2(xA, wv0.y, accA[1]);
                        accA[2] = ffma2(xA, wv1.x, accA[2]);
                        accA[3] = ffma2(xA, wv1.y, accA[3]);
                        accB[0] = ffma2(xB, wv0.x, accB[0]);
                        accB[1] = ffma2(xB, wv0.y, accB[1]);
                        accB[2] = ffma2(xB, wv1.x, accB[2]);
                        accB[3] = ffma2(xB, wv1.y, accB[3]);
                    }
                }
                __syncthreads();
            }
            // epilogue: f32x2 -> half2, transpose via smem, coalesced store
            {
                int cbase = (wid & 3) * 4;
                int hilo = (wid >> 2);
#pragma unroll
                for (int j = 0; j < 4; j++) {
                    float2 fa = unpk(accA[j]);
                    float2 fb = unpk(accB[j]);
                    int idx = 2 * (cbase + j) + hilo;
                    sEpiH[lane * 33 + idx] = f2h2(fa.x, fa.y);
                    sEpiH[(lane + 32) * 33 + idx] = f2h2(fb.x, fb.y);
                }
            }
            __syncthreads();
            u32* xw1u = (u32*)g_xw1h2;
            for (int i = tid; i < 2048; i += BS) {
                int r = i >> 5, s = i & 31;
                if (row0 + r < N)
                    xw1u[(size_t)(row0 + r) * 32 + s] = sEpiH[r * 33 + s];
            }
            __syncthreads();
        }
    }
    gbar(ebase + 2);

    // ---------------- phase C: dinv + per-chunk(256) count scan -------------
    {
        const int r0 = b * 256 + tid;
        int c0 = 0;
        if (r0 < N) {
            u64 pc = g_degcnt[r0];
            c0 = (int)(pc >> 42);
            g_dinv[r0] = rsqrtf(1.0f + (float)(pc & ((1ull << 42) - 1)) * (1.0f / 16777216.0f));
        }
        s_scan[tid] = c0;
        __syncthreads();
        for (int off = 1; off < BS; off <<= 1) {
            int a = (tid >= off) ? s_scan[tid - off] : 0;
            __syncthreads();
            s_scan[tid] += a;
            __syncthreads();
        }
        if (r0 < N) g_rowptr[r0] = s_scan[tid] - c0;
        if (tid == BS - 1) g_bsums[b] = s_scan[BS - 1];
    }
    gbar(ebase + 3);

    // ---------------- phase F: block-prefix + fill + fp16 prescale ----------
    {
        int i0 = tid, i1 = tid + 256;
        int v0 = g_bsums[i0], v1 = g_bsums[i1];
        s_pfx[i0] = v0; s_pfx[i1] = v1;
        __syncthreads();
        for (int off = 1; off < 512; off <<= 1) {
            int a0 = (i0 >= off) ? s_pfx[i0 - off] : 0;
            int a1 = (i1 >= off) ? s_pfx[i1 - off] : 0;
            __syncthreads();
            s_pfx[i0] += a0; s_pfx[i1] += a1;
            __syncthreads();
        }
        s_pfx[i0] -= v0; s_pfx[i1] -= v1;
        __syncthreads();
    }
    for (int e = gtid; e < E; e += NT) {
        int s, d;
        if (is64) {
            const long long* p = (const long long*)ei;
            s = (int)p[e]; d = (int)p[(size_t)E + e];
        } else {
            const int* p = (const int*)ei;
            s = p[e]; d = p[(size_t)E + e];
        }
        int slot = g_rowptr[d] + s_pfx[d >> 8] + (int)g_slot[e];
        g_csr[slot] = ((u64)__float_as_uint(ew[e]) << 32) | (u32)s;
    }
    {
        u32* xw1u = (u32*)g_xw1h2;
        for (int i = gtid; i < N * 32; i += NT) {     // prescale xw1 by dinv
            int row = i >> 5;
            float dn = g_dinv[row];
            float2 f = h2f2(xw1u[i]);
            xw1u[i] = f2h2(dn * f.x, dn * f.y);
        }
    }
    gbar(ebase + 4);

    // ---------------- phase G: SpMM1, 4x8-lane slots, LDG.128 gathers -------
    for (int i = tid; i < HID * CLS; i += BS) {
        int k = i >> 5, c = i & 31;
        float v = W2[k * CLS + c];
        int c2 = (k & 31) >> 1;
        float* base = (float*)((k >= 32) ? s_w2b : s_w2a);
        base[(c2 * 32 + c) * 2 + (k & 1)] = v;
    }
    if (tid < 64) s_b1v[tid] = b1[tid];
    if (tid < 32) s_b2v[tid] = b2[tid];
    __syncthreads();
    const int slot = lane >> 3, cc8 = lane & 7;
    u64* buf = s_ebuf[wid];
    for (;;) {
        int chunk;
        if (lane == 0) chunk = atomicAdd(&g_tickets[1], 1) - s_tb1;
        chunk = __shfl_sync(0xffffffffu, chunk, 0);
        int row0c = chunk * 8;
        if (row0c >= N) break;
        int row1c = row0c + 8 < N ? row0c + 8 : N;
        for (int row = row0c; row < row1c; row++) {
            float a0 = 0.f, a1 = 0.f, a2 = 0.f, a3 = 0.f;
            float a4 = 0.f, a5 = 0.f, a6 = 0.f, a7 = 0.f;
            if (slot == 0) {                       // prescaled self row
                ulonglong2 sv = g_xw1h2[(size_t)row * 8 + cc8];
                float2 f;
                f = h2f2((u32)sv.x);         a0 = f.x; a1 = f.y;
                f = h2f2((u32)(sv.x >> 32)); a2 = f.x; a3 = f.y;
                f = h2f2((u32)sv.y);         a4 = f.x; a5 = f.y;
                f = h2f2((u32)(sv.y >> 32)); a6 = f.x; a7 = f.y;
            }
            int p = g_rowptr[row] + s_pfx[row >> 8];
            int pe = (row + 1 < N) ? (g_rowptr[row + 1] + s_pfx[(row + 1) >> 8]) : E;
            while (p < pe) {
                int m = pe - p; if (m > 32) m = 32;
                buf[lane] = (lane < m) ? g_csr[p + lane] : 0ull;
                __syncwarp();
                int nst = (m + 3) >> 2;
                int t = 0;
                for (; t + 2 <= nst; t += 2) {     // 8 edges, 2 gathers in flight
                    u64 q0 = buf[4 * t + slot];
                    u64 q1 = buf[4 * t + 4 + slot];
                    ulonglong2 v0 = g_xw1h2[(size_t)(u32)q0 * 8 + cc8];
                    ulonglong2 v1 = g_xw1h2[(size_t)(u32)q1 * 8 + cc8];
                    float w0 = __uint_as_float((u32)(q0 >> 32));
                    float w1 = __uint_as_float((u32)(q1 >> 32));
                    float2 f;
                    f = h2f2((u32)v0.x);         a0 = fmaf(w0, f.x, a0); a1 = fmaf(w0, f.y, a1);
                    f = h2f2((u32)(v0.x >> 32)); a2 = fmaf(w0, f.x, a2); a3 = fmaf(w0, f.y, a3);
                    f = h2f2((u32)v0.y);         a4 = fmaf(w0, f.x, a4); a5 = fmaf(w0, f.y, a5);
                    f = h2f2((u32)(v0.y >> 32)); a6 = fmaf(w0, f.x, a6); a7 = fmaf(w0, f.y, a7);
                    f = h2f2((u32)v1.x);         a0 = fmaf(w1, f.x, a0); a1 = fmaf(w1, f.y, a1);
                    f = h2f2((u32)(v1.x >> 32)); a2 = fmaf(w1, f.x, a2); a3 = fmaf(w1, f.y, a3);
                    f = h2f2((u32)v1.y);         a4 = fmaf(w1, f.x, a4); a5 = fmaf(w1, f.y, a5);
                    f = h2f2((u32)(v1.y >> 32)); a6 = fmaf(w1, f.x, a6); a7 = fmaf(w1, f.y, a7);
                }
                for (; t < nst; t++) {
                    u64 q0 = buf[4 * t + slot];
                    ulonglong2 v0 = g_xw1h2[(size_t)(u32)q0 * 8 + cc8];
                    float w0 = __uint_as_float((u32)(q0 >> 32));
                    float2 f;
                    f = h2f2((u32)v0.x);         a0 = fmaf(w0, f.x, a0); a1 = fmaf(w0, f.y, a1);
                    f = h2f2((u32)(v0.x >> 32)); a2 = fmaf(w0, f.x, a2); a3 = fmaf(w0, f.y, a3);
                    f = h2f2((u32)v0.y);         a4 = fmaf(w0, f.x, a4); a5 = fmaf(w0, f.y, a5);
                    f = h2f2((u32)(v0.y >> 32)); a6 = fmaf(w0, f.x, a6); a7 = fmaf(w0, f.y, a7);
                }
                __syncwarp();
                p += 32;
            }
            // slot reduction (MIO, not LSU)
            a0 += __shfl_xor_sync(0xffffffffu, a0, 8);  a0 += __shfl_xor_sync(0xffffffffu, a0, 16);
            a1 += __shfl_xor_sync(0xffffffffu, a1, 8);  a1 += __shfl_xor_sync(0xffffffffu, a1, 16);
            a2 += __shfl_xor_sync(0xffffffffu, a2, 8);  a2 += __shfl_xor_sync(0xffffffffu, a2, 16);
            a3 += __shfl_xor_sync(0xffffffffu, a3, 8);  a3 += __shfl_xor_sync(0xffffffffu, a3, 16);
            a4 += __shfl_xor_sync(0xffffffffu, a4, 8);  a4 += __shfl_xor_sync(0xffffffffu, a4, 16);
            a5 += __shfl_xor_sync(0xffffffffu, a5, 8);  a5 += __shfl_xor_sync(0xffffffffu, a5, 16);
            a6 += __shfl_xor_sync(0xffffffffu, a6, 8);  a6 += __shfl_xor_sync(0xffffffffu, a6, 16);
            a7 += __shfl_xor_sync(0xffffffffu, a7, 8);  a7 += __shfl_xor_sync(0xffffffffu, a7, 16);
            float dn = g_dinv[row];
            if (slot == 0) {
                float4 bA = ((const float4*)s_b1v)[cc8];       // cols 4cc8..+3
                float4 bB = ((const float4*)s_b1v)[8 + cc8];   // cols 32+4cc8..+3
                float4 h0 = make_float4(fmaxf(dn * a0 + bA.x, 0.f),
                                        fmaxf(dn * a1 + bA.y, 0.f),
                                        fmaxf(dn * a2 + bB.x, 0.f),
                                        fmaxf(dn * a3 + bB.y, 0.f));
                float4 h1 = make_float4(fmaxf(dn * a4 + bA.z, 0.f),
                                        fmaxf(dn * a5 + bA.w, 0.f),
                                        fmaxf(dn * a6 + bB.z, 0.f),
                                        fmaxf(dn * a7 + bB.w, 0.f));
                ((float4*)s_hrow[wid])[2 * cc8] = h0;
                ((float4*)s_hrow[wid])[2 * cc8 + 1] = h1;
            }
            __syncwarp();
            // projection (f32x2): out col = lane (unchanged from r13)
            u64 accp = 0ull;
            const float4* hr = (const float4*)s_hrow[wid];
#pragma unroll
            for (int c2 = 0; c2 < 16; c2++) {
                float4 hv = hr[c2];
                accp = ffma2(pack2f(hv.x, hv.y), s_w2a[c2 * 32 + lane], accp);
                accp = ffma2(pack2f(hv.z, hv.w), s_w2b[c2 * 32 + lane], accp);
            }
            float2 ap = unpk(accp);
            ((float*)(g_xw2v + (size_t)row * 8))[lane] = dn * (ap.x + ap.y);
            __syncwarp();
        }
    }
    gbar(ebase + 5);

    // ---------------- phase H: SpMM2, 4x8-lane slots, LDG.128 -> out --------
    {
        for (;;) {
            int chunk;
            if (lane == 0) chunk = atomicAdd(&g_tickets[2], 1) - s_tb2;
            chunk = __shfl_sync(0xffffffffu, chunk, 0);
            int row0c = chunk * 8;
            if (row0c >= N) break;
            int row1c = row0c + 8 < N ? row0c + 8 : N;
            for (int row = row0c; row < row1c; row++) {
                u64 acc0 = 0ull, acc1 = 0ull;
                if (slot == 0) {                   // prescaled self row
                    ulonglong2 sv = g_xw2v[(size_t)row * 8 + cc8];
                    acc0 = sv.x; acc1 = sv.y;
                }
                int p = g_rowptr[row] + s_pfx[row >> 8];
                int pe = (row + 1 < N) ? (g_rowptr[row + 1] + s_pfx[(row + 1) >> 8]) : E;
                while (p < pe) {
                    int m = pe - p; if (m > 32) m = 32;
                    buf[lane] = (lane < m) ? g_csr[p + lane] : 0ull;
                    __syncwarp();
                    int nst = (m + 3) >> 2;
                    int t = 0;
                    for (; t + 4 <= nst; t += 4) { // 16 edges, 4 gathers in flight
                        u64 q0 = buf[4 * t + slot],      q1 = buf[4 * t + 4 + slot];
                        u64 q2 = buf[4 * t + 8 + slot],  q3 = buf[4 * t + 12 + slot];
                        ulonglong2 v0 = g_xw2v[(size_t)(u32)q0 * 8 + cc8];
                        ulonglong2 v1 = g_xw2v[(size_t)(u32)q1 * 8 + cc8];
                        ulonglong2 v2 = g_xw2v[(size_t)(u32)q2 * 8 + cc8];
                        ulonglong2 v3 = g_xw2v[(size_t)(u32)q3 * 8 + cc8];
                        acc0 = ffma2(dup2((u32)(q0 >> 32)), v0.x, acc0);
                        acc1 = ffma2(dup2((u32)(q0 >> 32)), v0.y, acc1);
                        acc0 = ffma2(dup2((u32)(q1 >> 32)), v1.x, acc0);
                        acc1 = ffma2(dup2((u32)(q1 >> 32)), v1.y, acc1);
                        acc0 = ffma2(dup2((u32)(q2 >> 32)), v2.x, acc0);
                        acc1 = ffma2(dup2((u32)(q2 >> 32)), v2.y, acc1);
                        acc0 = ffma2(dup2((u32)(q3 >> 32)), v3.x, acc0);
                        acc1 = ffma2(dup2((u32)(q3 >> 32)), v3.y, acc1);
                    }
                    for (; t < nst; t++) {
                        u64 q0 = buf[4 * t + slot];
                        ulonglong2 v0 = g_xw2v[(size_t)(u32)q0 * 8 + cc8];
                        acc0 = ffma2(dup2((u32)(q0 >> 32)), v0.x, acc0);
                        acc1 = ffma2(dup2((u32)(q0 >> 32)), v0.y, acc1);
                    }
                    __syncwarp();
                    p += 32;
                }
                float2 f0 = unpk(acc0), f1 = unpk(acc1);
                float r0 = f0.x, r1 = f0.y, r2 = f1.x, r3 = f1.y;
                r0 += __shfl_xor_sync(0xffffffffu, r0, 8);  r0 += __shfl_xor_sync(0xffffffffu, r0, 16);
                r1 += __shfl_xor_sync(0xffffffffu, r1, 8);  r1 += __shfl_xor_sync(0xffffffffu, r1, 16);
                r2 += __shfl_xor_sync(0xffffffffu, r2, 8);  r2 += __shfl_xor_sync(0xffffffffu, r2, 16);
                r3 += __shfl_xor_sync(0xffffffffu, r3, 8);  r3 += __shfl_xor_sync(0xffffffffu, r3, 16);
                if (slot == 0) {
                    float dn = g_dinv[row];
                    float4 bv = ((const float4*)s_b2v)[cc8];
                    ((float4*)(out + (size_t)row * CLS))[cc8] =
                        make_float4(dn * r0 + bv.x, dn * r1 + bv.y,
                                    dn * r2 + bv.z, dn * r3 + bv.w);
                }
            }
        }
    }

    // ---------------- tail: re-zero degcnt for the next replay --------------
    for (int i = gtid; i < N; i += NT) g_degcnt[i] = 0ull;
}

// ---------------------------------------------------------------------------
extern "C" void kernel_launch(void* const* d_in, const int* in_sizes, int n_in,
                              void* d_out, int out_size) {
    const float* x  = (const float*)d_in[0];
    const void*  ei = d_in[1];
    const float* ew = (const float*)d_in[2];
    const float* W1 = (const float*)d_in[3];
    const float* b1 = (const float*)d_in[4];
    const float* W2 = (const float*)d_in[5];
    const float* b2 = (const float*)d_in[6];
    float* out = (float*)d_out;

    int E = in_sizes[2];
    int N = in_sizes[0] / FIN1;
    if (N > N_MAXC) N = N_MAXC;
    if (E > E_MAXC) E = E_MAXC;

    mega<<<NB, BS>>>(x, ei, ew, W1, b1, W2, b2, out, N, E);
}

// round 17
// speedup vs baseline: 1.0731x; 1.0395x over previous
#include <cuda_runtime.h>
#include <cuda_fp16.h>
#include <stdint.h>

// ---------------------------------------------------------------------------
// 2-layer GCN, single persistent kernel. Round 17: r13 base + local LSU cuts.
//  (1) single LDS.64 edge decode in SpMM loops
//  (2) (dst<<15)|slot packed in phase B -> fill skips dst re-read
//  (3) prescale pass vectorized to 16B
// SpMM shape, GEMM, phases, barriers: identical to round 13 (best, 193.3us).
// ---------------------------------------------------------------------------

#define N_MAXC  100000
#define E_MAXC  1700000
#define FIN1    128
#define HID     64
#define CLS     32
#define NB      512
#define BS      256
#define NT      (NB * BS)

typedef unsigned long long u64;
typedef unsigned int u32;

// ---- device scratch ----
__device__ u64        g_degcnt[N_MAXC];        // (count<<42)|fixed24(sum ew); 0 at entry
__device__ u32        g_slot[E_MAXC];          // (dst<<15) | intra-bucket slot
__device__ int        g_rowptr[N_MAXC + 1];    // intra-chunk exclusive counts
__device__ float      g_dinv[N_MAXC];
__device__ int        g_bsums[NB];
__device__ u64        g_csr[E_MAXC];           // (f32bits(ew)<<32)|src
__device__ ulonglong2 g_xw1v2[(size_t)N_MAXC * 8];  // fp16 permuted xw1 (16B-ald)
__device__ ulonglong2 g_xw2v[(size_t)N_MAXC * 8];   // fp32 xw2
__device__ int        g_tickets[4];            // monotonic across runs
__device__ int        g_count;
__device__ int        g_gen;

// ---- packed f32x2 helpers ----
__device__ __forceinline__ u64 ffma2(u64 a, u64 b, u64 c) {
    u64 d;
    asm("fma.rn.f32x2 %0, %1, %2, %3;" : "=l"(d) : "l"(a), "l"(b), "l"(c));
    return d;
}
__device__ __forceinline__ u64 dup2(u32 w) {
    u64 d;
    asm("mov.b64 %0, {%1, %1};" : "=l"(d) : "r"(w));
    return d;
}
__device__ __forceinline__ u64 pack2f(float x, float y) {
    u64 d;
    asm("mov.b64 %0, {%1, %2};" : "=l"(d) : "r"(__float_as_uint(x)), "r"(__float_as_uint(y)));
    return d;
}
__device__ __forceinline__ float2 unpk(u64 v) {
    float2 f;
    asm("mov.b64 {%0, %1}, %2;" : "=f"(f.x), "=f"(f.y) : "l"(v));
    return f;
}
__device__ __forceinline__ u32 f2h2(float lo, float hi) {
    u32 r;
    asm("cvt.rn.f16x2.f32 %0, %1, %2;" : "=r"(r) : "f"(hi), "f"(lo));
    return r;
}
__device__ __forceinline__ float2 h2f2(u32 v) {
    __half2 h = *(__half2*)&v;
    return __half22float2(h);
}

// ---- grid barrier ----
__device__ __forceinline__ void gbar(int expect) {
    __syncthreads();
    if (threadIdx.x == 0) {
        __threadfence();
        int t = atomicAdd(&g_count, 1);
        if (t == NB - 1) {
            g_count = 0;
            __threadfence();
            *(volatile int*)&g_gen = expect;
        } else {
            while (*(volatile int*)&g_gen - expect < 0) {}
            __threadfence();
        }
    }
    __syncthreads();
}

__global__ void __launch_bounds__(BS, 4) mega(
    const float* __restrict__ x, const void* __restrict__ ei,
    const float* __restrict__ ew, const float* __restrict__ W1,
    const float* __restrict__ b1, const float* __restrict__ W2,
    const float* __restrict__ b2, float* __restrict__ out,
    int N, int E)
{
    __shared__ __align__(16) char s_mem[33792 + 4096];
    __shared__ int s_is64, s_tile, s_tb0, s_tb1, s_tb2;

    float* sX   = (float*)s_mem;                  // GEMM: [64][132]
    float* sW   = (float*)(s_mem + 33792);        // GEMM: [16][64]
    u32*   sEpiH = (u32*)s_mem;                   // GEMM epi: [64][33] u32 (half2)
    int*   s_scan = (int*)s_mem;                  // C scan
    u64*   s_w2a = (u64*)s_mem;                   // proj pairs lo
    u64*   s_w2b = (u64*)(s_mem + 4096);          // proj pairs hi
    u64 (*s_ebuf)[32] = (u64(*)[32])(s_mem + 8192);
    float (*s_hrow)[HID] = (float(*)[HID])(s_mem + 8192 + 2048);
    int*   s_pfx = (int*)(s_mem + 16384);         // block prefix, persists F..H

    const int tid = threadIdx.x;
    const int b   = blockIdx.x;
    const int gtid = b * BS + tid;
    const int wid = tid >> 5, lane = tid & 31;
    const u64* X1 = (const u64*)g_xw1v2;

    // ---------------- entry: bases + i32/i64 detect -------------------------
    int ebase = 0;
    if (tid == 0) {
        ebase = *(volatile int*)&g_gen;
        s_tb0 = *(volatile int*)&g_tickets[0];
        s_tb1 = *(volatile int*)&g_tickets[1];
        s_tb2 = *(volatile int*)&g_tickets[2];
    }
    if (tid < 32) {
        const u32* u = (const u32*)ei;
        int cnt = E < 64 ? E : 64;
        bool nz = false;
        for (int j = tid; j < cnt; j += 32) nz |= (u[2 * j + 1] != 0u);
        u32 bl = __ballot_sync(0xffffffffu, nz);
        if (tid == 0) s_is64 = (bl == 0u) ? 1 : 0;
    }
    gbar(ebase + 1);
    const int is64 = s_is64;

    // ---------------- phase B: edge atomics+packed slots + GEMM -------------
    for (int e = gtid; e < E; e += NT) {
        int d = is64 ? (int)((const long long*)ei)[(size_t)E + e]
                     : ((const int*)ei)[(size_t)E + e];
        u64 add = (1ull << 42) | (u64)(u32)__float2uint_rn(ew[e] * 16777216.0f);
        u64 old = atomicAdd(&g_degcnt[d], add);
        g_slot[e] = ((u32)d << 15) | (u32)(old >> 42);   // deg << 2^15 (Poisson ~16)
    }
    {
        const int ntiles = (N + 63) / 64;
        const int w8 = wid * 8;
        for (;;) {
            if (tid == 0) s_tile = atomicAdd(&g_tickets[0], 1) - s_tb0;
            __syncthreads();
            const int tile = s_tile;
            if (tile >= ntiles) break;
            const int row0 = tile * 64;
            for (int i = tid; i < 2048; i += BS) {
                int r = i >> 5, k4 = i & 31;
                float4 v = make_float4(0.f, 0.f, 0.f, 0.f);
                if (row0 + r < N)
                    v = ((const float4*)(x + (size_t)(row0 + r) * FIN1))[k4];
                *(float4*)&sX[r * 132 + 4 * k4] = v;
            }
            __syncthreads();

            u64 accA[4], accB[4];
#pragma unroll
            for (int j = 0; j < 4; j++) { accA[j] = 0ull; accB[j] = 0ull; }

            for (int c = 0; c < 8; c++) {
                {
                    int k = tid >> 4, c4 = tid & 15;
                    *(float4*)&sW[k * 64 + 4 * c4] =
                        ((const float4*)(W1 + (size_t)(c * 16 + k) * HID))[c4];
                }
                __syncthreads();
                const float4* xpA = (const float4*)&sX[lane * 132 + c * 16];
                const float4* xpB = (const float4*)&sX[(lane + 32) * 132 + c * 16];
#pragma unroll
                for (int k4 = 0; k4 < 4; k4++) {
                    float4 xa = xpA[k4];
                    float4 xb = xpB[k4];
                    float xsA[4] = {xa.x, xa.y, xa.z, xa.w};
                    float xsB[4] = {xb.x, xb.y, xb.z, xb.w};
#pragma unroll
                    for (int kk = 0; kk < 4; kk++) {
                        int k = k4 * 4 + kk;
                        ulonglong2 wv0 = *(const ulonglong2*)&sW[k * 64 + w8];
                        ulonglong2 wv1 = *(const ulonglong2*)&sW[k * 64 + w8 + 4];
                        u64 xA = dup2(__float_as_uint(xsA[kk]));
                        u64 xB = dup2(__float_as_uint(xsB[kk]));
                        accA[0] = ffma2(xA, wv0.x, accA[0]);
                        accA[1] = ffma2(xA, wv0.y, accA[1]);
                        accA[2] = ffma2(xA, wv1.x, accA[2]);
                        accA[3] = ffma2(xA, wv1.y, accA[3]);
                        accB[0] = ffma2(xB, wv0.x, accB[0]);
                        accB[1] = ffma2(xB, wv0.y, accB[1]);
                        accB[2] = ffma2(xB, wv1.x, accB[2]);
                        accB[3] = ffma2(xB, wv1.y, accB[3]);
                    }
                }
                __syncthreads();
            }
            // epilogue: f32x2 -> half2, transpose via smem, coalesced store
            {
                int cbase = (wid & 3) * 4;
                int hilo = (wid >> 2);
#pragma unroll
                for (int j = 0; j < 4; j++) {
                    float2 fa = unpk(accA[j]);
                    float2 fb = unpk(accB[j]);
                    int idx = 2 * (cbase + j) + hilo;
                    sEpiH[lane * 33 + idx] = f2h2(fa.x, fa.y);
                    sEpiH[(lane + 32) * 33 + idx] = f2h2(fb.x, fb.y);
                }
            }
            __syncthreads();
            u32* xw1u = (u32*)g_xw1v2;
            for (int i = tid; i < 2048; i += BS) {
                int r = i >> 5, s = i & 31;
                if (row0 + r < N)
                    xw1u[(size_t)(row0 + r) * 32 + s] = sEpiH[r * 33 + s];
            }
            __syncthreads();
        }
    }
    gbar(ebase + 2);

    // ---------------- phase C: dinv + per-chunk(256) count scan -------------
    {
        const int r0 = b * 256 + tid;
        int c0 = 0;
        if (r0 < N) {
            u64 pc = g_degcnt[r0];
            c0 = (int)(pc >> 42);
            g_dinv[r0] = rsqrtf(1.0f + (float)(pc & ((1ull << 42) - 1)) * (1.0f / 16777216.0f));
        }
        s_scan[tid] = c0;
        __syncthreads();
        for (int off = 1; off < BS; off <<= 1) {
            int a = (tid >= off) ? s_scan[tid - off] : 0;
            __syncthreads();
            s_scan[tid] += a;
            __syncthreads();
        }
        if (r0 < N) g_rowptr[r0] = s_scan[tid] - c0;
        if (tid == BS - 1) g_bsums[b] = s_scan[BS - 1];
    }
    gbar(ebase + 3);

    // ---------------- phase F: block-prefix + fill + fp16 prescale ----------
    {
        int i0 = tid, i1 = tid + 256;
        int v0 = g_bsums[i0], v1 = g_bsums[i1];
        s_pfx[i0] = v0; s_pfx[i1] = v1;
        __syncthreads();
        for (int off = 1; off < 512; off <<= 1) {
            int a0 = (i0 >= off) ? s_pfx[i0 - off] : 0;
            int a1 = (i1 >= off) ? s_pfx[i1 - off] : 0;
            __syncthreads();
            s_pfx[i0] += a0; s_pfx[i1] += a1;
            __syncthreads();
        }
        s_pfx[i0] -= v0; s_pfx[i1] -= v1;
        __syncthreads();
    }
    for (int e = gtid; e < E; e += NT) {              // fill: no dst re-read
        u32 pk = g_slot[e];
        int d = (int)(pk >> 15);
        int sl = (int)(pk & 0x7FFFu);
        int s = is64 ? (int)((const long long*)ei)[e] : ((const int*)ei)[e];
        int slot = g_rowptr[d] + s_pfx[d >> 8] + sl;
        g_csr[slot] = ((u64)__float_as_uint(ew[e]) << 32) | (u32)s;
    }
    {
        // prescale xw1 by dinv: 16B per thread-iteration
        for (int i = gtid; i < N * 8; i += NT) {
            int row = i >> 3;
            float dn = g_dinv[row];
            ulonglong2 v = g_xw1v2[i];
            u32 w0 = (u32)v.x, w1 = (u32)(v.x >> 32);
            u32 w2 = (u32)v.y, w3 = (u32)(v.y >> 32);
            float2 f0 = h2f2(w0), f1 = h2f2(w1), f2 = h2f2(w2), f3 = h2f2(w3);
            w0 = f2h2(dn * f0.x, dn * f0.y);
            w1 = f2h2(dn * f1.x, dn * f1.y);
            w2 = f2h2(dn * f2.x, dn * f2.y);
            w3 = f2h2(dn * f3.x, dn * f3.y);
            ulonglong2 o;
            o.x = (u64)w0 | ((u64)w1 << 32);
            o.y = (u64)w2 | ((u64)w3 << 32);
            g_xw1v2[i] = o;
        }
    }
    gbar(ebase + 4);

    // ---------------- phase G: SpMM1 (fp16, u64 decode) + proj --------------
    for (int i = tid; i < HID * CLS; i += BS) {
        int k = i >> 5, c = i & 31;
        float v = W2[k * CLS + c];
        int c2 = (k & 31) >> 1;
        float* base = (float*)((k >= 32) ? s_w2b : s_w2a);
        base[(c2 * 32 + c) * 2 + (k & 1)] = v;
    }
    __syncthreads();
    const int slot = lane >> 4, cc = lane & 15;
    float b1a = b1[2 * cc], b1b = b1[2 * cc + 1];
    float b1c = b1[32 + 2 * cc], b1d = b1[33 + 2 * cc];
    u64* buf = s_ebuf[wid];
    for (;;) {
        int chunk;
        if (lane == 0) chunk = atomicAdd(&g_tickets[1], 1) - s_tb1;
        chunk = __shfl_sync(0xffffffffu, chunk, 0);
        int row0c = chunk * 8;
        if (row0c >= N) break;
        int row1c = row0c + 8 < N ? row0c + 8 : N;
        for (int row = row0c; row < row1c; row++) {
            float dn = g_dinv[row];
            float a0 = 0.f, a1 = 0.f, a2 = 0.f, a3 = 0.f;
            if (slot == 0) {
                u64 sv = X1[(size_t)row * 16 + cc];    // prescaled self
                float2 flo = h2f2((u32)sv), fhi = h2f2((u32)(sv >> 32));
                a0 = flo.x; a1 = flo.y; a2 = fhi.x; a3 = fhi.y;
            }
            int p = g_rowptr[row] + s_pfx[row >> 8];
            int pe = (row + 1 < N) ? (g_rowptr[row + 1] + s_pfx[(row + 1) >> 8]) : E;
            while (p < pe) {
                int m = pe - p; if (m > 32) m = 32;
                buf[lane] = (lane < m) ? g_csr[p + lane] : 0ull;
                __syncwarp();
                int pairs = (m + 1) >> 1;
                int t = 0;
                for (; t + 8 <= pairs; t += 8) {
                    u64 q[8], v[8];
#pragma unroll
                    for (int i = 0; i < 8; i++) q[i] = buf[2 * (t + i) + slot];
#pragma unroll
                    for (int i = 0; i < 8; i++)
                        v[i] = X1[(size_t)(u32)q[i] * 16 + cc];
#pragma unroll
                    for (int i = 0; i < 8; i++) {
                        float w = __uint_as_float((u32)(q[i] >> 32));
                        float2 flo = h2f2((u32)v[i]), fhi = h2f2((u32)(v[i] >> 32));
                        a0 = fmaf(w, flo.x, a0); a1 = fmaf(w, flo.y, a1);
                        a2 = fmaf(w, fhi.x, a2); a3 = fmaf(w, fhi.y, a3);
                    }
                }
                for (; t < pairs; t++) {
                    u64 q0 = buf[2 * t + slot];
                    u64 v0 = X1[(size_t)(u32)q0 * 16 + cc];
                    float w = __uint_as_float((u32)(q0 >> 32));
                    float2 flo = h2f2((u32)v0), fhi = h2f2((u32)(v0 >> 32));
                    a0 = fmaf(w, flo.x, a0); a1 = fmaf(w, flo.y, a1);
                    a2 = fmaf(w, fhi.x, a2); a3 = fmaf(w, fhi.y, a3);
                }
                __syncwarp();
                p += 32;
            }
            a0 += __shfl_xor_sync(0xffffffffu, a0, 16);
            a1 += __shfl_xor_sync(0xffffffffu, a1, 16);
            a2 += __shfl_xor_sync(0xffffffffu, a2, 16);
            a3 += __shfl_xor_sync(0xffffffffu, a3, 16);
            float hx = fmaxf(dn * a0 + b1a, 0.0f);
            float hy = fmaxf(dn * a1 + b1b, 0.0f);
            float hz = fmaxf(dn * a2 + b1c, 0.0f);
            float hw = fmaxf(dn * a3 + b1d, 0.0f);
            if (slot == 0)
                ((float4*)s_hrow[wid])[cc] = make_float4(hx, hy, hz, hw);
            __syncwarp();
            u64 accp = 0ull;
            const float4* hr = (const float4*)s_hrow[wid];
#pragma unroll
            for (int c2 = 0; c2 < 16; c2++) {
                float4 hv = hr[c2];
                accp = ffma2(pack2f(hv.x, hv.y), s_w2a[c2 * 32 + lane], accp);
                accp = ffma2(pack2f(hv.z, hv.w), s_w2b[c2 * 32 + lane], accp);
            }
            float2 ap = unpk(accp);
            ((float*)(g_xw2v + (size_t)row * 8))[lane] = dn * (ap.x + ap.y);
            __syncwarp();
        }
    }
    gbar(ebase + 5);

    // ---------------- phase H: SpMM2 (u64 decode, MLP=8) -> out -------------
    {
        float2 b2v = ((const float2*)b2)[cc];
        const u64* X2 = (const u64*)g_xw2v;
        for (;;) {
            int chunk;
            if (lane == 0) chunk = atomicAdd(&g_tickets[2], 1) - s_tb2;
            chunk = __shfl_sync(0xffffffffu, chunk, 0);
            int row0c = chunk * 8;
            if (row0c >= N) break;
            int row1c = row0c + 8 < N ? row0c + 8 : N;
            for (int row = row0c; row < row1c; row++) {
                float dn = g_dinv[row];
                u64 acc = 0ull;
                if (slot == 0) acc = X2[(size_t)row * 16 + cc];   // prescaled
                int p = g_rowptr[row] + s_pfx[row >> 8];
                int pe = (row + 1 < N) ? (g_rowptr[row + 1] + s_pfx[(row + 1) >> 8]) : E;
                while (p < pe) {
                    int m = pe - p; if (m > 32) m = 32;
                    buf[lane] = (lane < m) ? g_csr[p + lane] : 0ull;
                    __syncwarp();
                    int pairs = (m + 1) >> 1;
                    int t = 0;
                    for (; t + 8 <= pairs; t += 8) {
                        u64 q[8], v[8];
#pragma unroll
                        for (int i = 0; i < 8; i++) q[i] = buf[2 * (t + i) + slot];
#pragma unroll
                        for (int i = 0; i < 8; i++)
                            v[i] = X2[(size_t)(u32)q[i] * 16 + cc];
#pragma unroll
                        for (int i = 0; i < 8; i++)
                            acc = ffma2(dup2((u32)(q[i] >> 32)), v[i], acc);
                    }
                    for (; t < pairs; t++) {
                        u64 q0 = buf[2 * t + slot];
                        acc = ffma2(dup2((u32)(q0 >> 32)),
                                    X2[(size_t)(u32)q0 * 16 + cc], acc);
                    }
                    __syncwarp();
                    p += 32;
                }
                float2 a = unpk(acc);
                a.x += __shfl_xor_sync(0xffffffffu, a.x, 16);
                a.y += __shfl_xor_sync(0xffffffffu, a.y, 16);
                if (slot == 0)
                    ((float2*)(out + (size_t)row * CLS))[cc] =
                        make_float2(dn * a.x + b2v.x, dn * a.y + b2v.y);
            }
        }
    }

    // ---------------- tail: re-zero degcnt for the next replay --------------
    for (int i = gtid; i < N; i += NT) g_degcnt[i] = 0ull;
}

// ---------------------------------------------------------------------------
extern "C" void kernel_launch(void* const* d_in, const int* in_sizes, int n_in,
                              void* d_out, int out_size) {
    const float* x  = (const float*)d_in[0];
    const void*  ei = d_in[1];
    const float* ew = (const float*)d_in[2];
    const float* W1 = (const float*)d_in[3];
    const float* b1 = (const float*)d_in[4];
    const float* W2 = (const float*)d_in[5];
    const float* b2 = (const float*)d_in[6];
    float* out = (float*)d_out;

    int E = in_sizes[2];
    int N = in_sizes[0] / FIN1;
    if (N > N_MAXC) N = N_MAXC;
    if (E > E_MAXC) E = E_MAXC;

    mega<<<NB, BS>>>(x, ei, ew, W1, b1, W2, b2, out, N, E);
}